// round 8
// baseline (speedup 1.0000x reference)
#include <cuda_runtime.h>
#include <math.h>

#define BB   128
#define SS   512
#define DD   512
#define TT   64
#define OUTD 3
#define GG   (3*DD)        // 1536
#define KIN  (DD+OUTD)     // 515

// ---------------- scratch (device globals: allocation-free) ----------------
__device__ float g_Uk[(size_t)BB*SS*DD];   // [B,S,D] precomputed Ua(keys)+bu
__device__ float g_h  [BB*DD];             // decoder hidden state
__device__ float g_qp [4*BB*DD];           // split-K partials of q = h@Wa^T
__device__ float g_gin[BB*KIN];            // [ctx | x_t]
__device__ float g_gip[4*BB*GG];           // split-K partials of gi
__device__ float g_ghp[4*BB*GG];           // split-K partials of gh

// fast, accurate-enough (≈1e-6 rel) transcendentals on MUFU
__device__ __forceinline__ float tanh_fast(float x) {
    return 1.f - __fdividef(2.f, __expf(2.f*x) + 1.f);
}
__device__ __forceinline__ float sigmoid_fast(float x) {
    return __fdividef(1.f, 1.f + __expf(-x));
}

// ---------------- init: h0 = e_last ----------------
__global__ void init_h_kernel(const float* __restrict__ e_last) {
    int i = blockIdx.x * blockDim.x + threadIdx.x;
    if (i < BB*DD) g_h[i] = e_last[i];
}

// ---------------- Uk GEMM: g_Uk[r,e] = sum_d e_all[r,d]*Ua[e,d] + bu[e] ----
// M=65536, N=512, K=512. BM=128, BN=64, BK=16, 256 threads, 8x4 per thread.
__global__ __launch_bounds__(256) void uk_gemm(const float* __restrict__ A,
                                               const float* __restrict__ W,
                                               const float* __restrict__ bias) {
    __shared__ float Xs[16][128];
    __shared__ float Ws[16][64];
    const int tid = threadIdx.x;
    const int tx = tid & 15, ty = tid >> 4;
    const int row0 = blockIdx.y * 128;
    const int n0   = blockIdx.x * 64;

    float acc[8][4];
#pragma unroll
    for (int i = 0; i < 8; i++)
#pragma unroll
        for (int j = 0; j < 4; j++) acc[i][j] = 0.f;

    for (int kc = 0; kc < 512; kc += 16) {
#pragma unroll
        for (int i = 0; i < 2; i++) {
            int l4 = tid*2 + i;                 // 0..511 float4 slots
            int r = l4 >> 2, kq = (l4 & 3) << 2;
            float4 v = *(const float4*)(A + (size_t)(row0 + r)*512 + kc + kq);
            Xs[kq+0][r] = v.x; Xs[kq+1][r] = v.y; Xs[kq+2][r] = v.z; Xs[kq+3][r] = v.w;
        }
        {
            int n = tid >> 2, kq = (tid & 3) << 2;
            float4 v = *(const float4*)(W + (size_t)(n0 + n)*512 + kc + kq);
            Ws[kq+0][n] = v.x; Ws[kq+1][n] = v.y; Ws[kq+2][n] = v.z; Ws[kq+3][n] = v.w;
        }
        __syncthreads();
#pragma unroll
        for (int kk = 0; kk < 16; kk++) {
            float a[8], b[4];
#pragma unroll
            for (int i = 0; i < 8; i++) a[i] = Xs[kk][ty*8 + i];
#pragma unroll
            for (int j = 0; j < 4; j++) b[j] = Ws[kk][tx*4 + j];
#pragma unroll
            for (int i = 0; i < 8; i++)
#pragma unroll
                for (int j = 0; j < 4; j++) acc[i][j] += a[i]*b[j];
        }
        __syncthreads();
    }
#pragma unroll
    for (int i = 0; i < 8; i++) {
        size_t r = (size_t)(row0 + ty*8 + i);
#pragma unroll
        for (int j = 0; j < 4; j++) {
            int n = n0 + tx*4 + j;
            g_Uk[r*512 + n] = acc[i][j] + bias[n];
        }
    }
}

// ---------------- skinny GEMM with split-K=4: Cp[p][b][n] partials --------
// which: 0 -> X=g_h (K=512), out=g_qp (N=512)
//        1 -> X=g_gin (K=515), out=g_gip (N=1536)
//        2 -> X=g_h (K=512), out=g_ghp (N=1536)
// BM=128 (=B), BN=64, BK=16, 256 threads, 8x4.
__global__ __launch_bounds__(256) void skinny_gemm(const float* __restrict__ W,
                                                   int K, int N, int which) {
    __shared__ float Xs[16][128];
    __shared__ float Ws[16][64];
    const float* X; float* Cp;
    if      (which == 0) { X = g_h;   Cp = g_qp;  }
    else if (which == 1) { X = g_gin; Cp = g_gip; }
    else                 { X = g_h;   Cp = g_ghp; }

    const int tid = threadIdx.x;
    const int tx = tid & 15, ty = tid >> 4;
    const int n0 = blockIdx.x * 64;
    const int part = blockIdx.y;
    const int chunk = (K + 3) >> 2;
    const int kb = part * chunk;
    const int ke = (kb + chunk < K) ? (kb + chunk) : K;

    float acc[8][4];
#pragma unroll
    for (int i = 0; i < 8; i++)
#pragma unroll
        for (int j = 0; j < 4; j++) acc[i][j] = 0.f;

    for (int kc = kb; kc < ke; kc += 16) {
#pragma unroll
        for (int i = 0; i < 8; i++) {
            int l = tid*8 + i;                  // 0..2047
            int r = l >> 4, k = l & 15;
            int kg = kc + k;
            Xs[k][r] = (kg < ke) ? X[r*K + kg] : 0.f;
        }
#pragma unroll
        for (int i = 0; i < 4; i++) {
            int l = tid*4 + i;                  // 0..1023
            int n = l >> 4, k = l & 15;
            int kg = kc + k;
            Ws[k][n] = (kg < ke) ? W[(size_t)(n0 + n)*K + kg] : 0.f;
        }
        __syncthreads();
#pragma unroll
        for (int kk = 0; kk < 16; kk++) {
            float a[8], b[4];
#pragma unroll
            for (int i = 0; i < 8; i++) a[i] = Xs[kk][ty*8 + i];
#pragma unroll
            for (int j = 0; j < 4; j++) b[j] = Ws[kk][tx*4 + j];
#pragma unroll
            for (int i = 0; i < 8; i++)
#pragma unroll
                for (int j = 0; j < 4; j++) acc[i][j] += a[i]*b[j];
        }
        __syncthreads();
    }
#pragma unroll
    for (int i = 0; i < 8; i++) {
        int b = ty*8 + i;
        size_t base = ((size_t)part*BB + b) * (size_t)N + n0;
#pragma unroll
        for (int j = 0; j < 4; j++) Cp[base + tx*4 + j] = acc[i][j];
    }
}

// ---------------- attention: scores -> softmax -> ctx (one block per b) ---
__global__ __launch_bounds__(512) void attn_kernel(const float* __restrict__ e_all,
                                                   const float* __restrict__ target,
                                                   const float* __restrict__ ba,
                                                   const float* __restrict__ va,
                                                   const float* __restrict__ va_b,
                                                   float* __restrict__ out, int t) {
    const int b = blockIdx.x;
    const int tid = threadIdx.x;
    __shared__ __align__(16) float q_s[DD];
    __shared__ __align__(16) float w_s[SS];
    __shared__ float red[16];
    __shared__ float bval;

    // assemble q[b,:] = sum of split-K partials + ba
    {
        int off = b*DD + tid;
        q_s[tid] = ba[tid] + g_qp[off] + g_qp[BB*DD + off]
                 + g_qp[2*BB*DD + off] + g_qp[3*BB*DD + off];
    }
    __syncthreads();

    const int warp = tid >> 5, lane = tid & 31;
    // preload this lane's va / q slices into registers
    float vreg[16], qreg[16];
#pragma unroll
    for (int k = 0; k < 4; k++) {
        int d = lane*4 + k*128;
        float4 vv = *(const float4*)(va + d);
        float4 qq = *(const float4*)(&q_s[d]);
        vreg[k*4+0]=vv.x; vreg[k*4+1]=vv.y; vreg[k*4+2]=vv.z; vreg[k*4+3]=vv.w;
        qreg[k*4+0]=qq.x; qreg[k*4+1]=qq.y; qreg[k*4+2]=qq.z; qreg[k*4+3]=qq.w;
    }
    const float vb = va_b[0];

    // pass 1: scores (warp per s, 16 warps stride S)
    for (int s = warp; s < SS; s += 16) {
        const float* u = g_Uk + ((size_t)b*SS + s)*DD;
        float acc = 0.f;
#pragma unroll
        for (int k = 0; k < 4; k++) {
            float4 uu = *(const float4*)(u + lane*4 + k*128);
            acc += vreg[k*4+0]*tanh_fast(qreg[k*4+0] + uu.x);
            acc += vreg[k*4+1]*tanh_fast(qreg[k*4+1] + uu.y);
            acc += vreg[k*4+2]*tanh_fast(qreg[k*4+2] + uu.z);
            acc += vreg[k*4+3]*tanh_fast(qreg[k*4+3] + uu.w);
        }
#pragma unroll
        for (int o = 16; o > 0; o >>= 1) acc += __shfl_xor_sync(0xffffffffu, acc, o);
        if (lane == 0) w_s[s] = acc + vb;
    }
    __syncthreads();

    // softmax over S (one thread per s)
    float sc = w_s[tid];
    float m = sc;
#pragma unroll
    for (int o = 16; o > 0; o >>= 1) m = fmaxf(m, __shfl_xor_sync(0xffffffffu, m, o));
    if (lane == 0) red[warp] = m;
    __syncthreads();
    if (tid == 0) {
        float mm = red[0];
#pragma unroll
        for (int i = 1; i < 16; i++) mm = fmaxf(mm, red[i]);
        bval = mm;
    }
    __syncthreads();
    float ex = __expf(sc - bval);
    float sm = ex;
#pragma unroll
    for (int o = 16; o > 0; o >>= 1) sm += __shfl_xor_sync(0xffffffffu, sm, o);
    if (lane == 0) red[warp] = sm;
    __syncthreads();
    if (tid == 0) {
        float tt = 0.f;
#pragma unroll
        for (int i = 0; i < 16; i++) tt += red[i];
        bval = tt;
    }
    __syncthreads();
    float wv = __fdividef(ex, bval);
    w_s[tid] = wv;
    out[(size_t)(BB*TT*OUTD + BB*DD) + ((size_t)b*TT + t)*SS + tid] = wv;
    __syncthreads();

    // pass 2: ctx[b,d] = sum_s w[s]*e_all[b,s,d]  (thread = d)
    const float* eb = e_all + (size_t)b*SS*DD + tid;
    float a0=0.f, a1=0.f, a2=0.f, a3=0.f;
    for (int s = 0; s < SS; s += 4) {
        a0 += w_s[s+0]*eb[(size_t)(s+0)*DD];
        a1 += w_s[s+1]*eb[(size_t)(s+1)*DD];
        a2 += w_s[s+2]*eb[(size_t)(s+2)*DD];
        a3 += w_s[s+3]*eb[(size_t)(s+3)*DD];
    }
    g_gin[b*KIN + tid] = (a0 + a1) + (a2 + a3);
    // teacher-forced decoder input (attn first, x second)
    if (tid < OUTD)
        g_gin[b*KIN + DD + tid] = (t == 0) ? 0.f
                                  : target[((size_t)b*TT + (t-1))*OUTD + tid];
}

// ---------------- GRU pointwise + output projection (block per b) ---------
__global__ __launch_bounds__(512) void point_kernel(const float* __restrict__ b_ih,
                                                    const float* __restrict__ b_hh,
                                                    const float* __restrict__ W_out,
                                                    const float* __restrict__ b_out,
                                                    float* __restrict__ out, int t) {
    const int b = blockIdx.x, d = threadIdx.x;
    const int base = b*DD + d;

    float ir = b_ih[d], iz = b_ih[DD+d], in_ = b_ih[2*DD+d];
    float hr = b_hh[d], hz = b_hh[DD+d], hn  = b_hh[2*DD+d];
#pragma unroll
    for (int p = 0; p < 4; p++) {
        size_t o = ((size_t)p*BB + b)*GG;
        ir += g_gip[o + d]; iz += g_gip[o + DD + d]; in_ += g_gip[o + 2*DD + d];
        hr += g_ghp[o + d]; hz += g_ghp[o + DD + d]; hn  += g_ghp[o + 2*DD + d];
    }
    float r = sigmoid_fast(ir + hr);
    float z = sigmoid_fast(iz + hz);
    float n = tanh_fast(in_ + r*hn);
    float hp = g_h[base];
    float hnew = (1.f - z)*n + z*hp;
    g_h[base] = hnew;
    if (t == TT-1) out[BB*TT*OUTD + base] = hnew;   // hT region

    // out = h_new @ W_out^T + b_out  (3 block-wide dot products)
    float p0 = hnew*W_out[d], p1 = hnew*W_out[DD+d], p2 = hnew*W_out[2*DD+d];
#pragma unroll
    for (int o = 16; o > 0; o >>= 1) {
        p0 += __shfl_xor_sync(0xffffffffu, p0, o);
        p1 += __shfl_xor_sync(0xffffffffu, p1, o);
        p2 += __shfl_xor_sync(0xffffffffu, p2, o);
    }
    __shared__ float r0[16], r1[16], r2[16];
    int warp = d >> 5, lane = d & 31;
    if (lane == 0) { r0[warp] = p0; r1[warp] = p1; r2[warp] = p2; }
    __syncthreads();
    if (d == 0) {
        float s0=0.f, s1=0.f, s2=0.f;
#pragma unroll
        for (int i = 0; i < 16; i++) { s0 += r0[i]; s1 += r1[i]; s2 += r2[i]; }
        size_t ob = ((size_t)b*TT + t)*OUTD;
        out[ob+0] = s0 + b_out[0];
        out[ob+1] = s1 + b_out[1];
        out[ob+2] = s2 + b_out[2];
    }
}

// ---------------- host launcher -------------------------------------------
extern "C" void kernel_launch(void* const* d_in, const int* in_sizes, int n_in,
                              void* d_out, int out_size) {
    (void)in_sizes; (void)n_in; (void)out_size;
    const float* e_all  = (const float*)d_in[0];
    const float* e_last = (const float*)d_in[1];
    const float* target = (const float*)d_in[2];
    const float* Wa     = (const float*)d_in[3];
    const float* ba     = (const float*)d_in[4];
    const float* Ua     = (const float*)d_in[5];
    const float* bu     = (const float*)d_in[6];
    const float* Va_w   = (const float*)d_in[7];
    const float* Va_b   = (const float*)d_in[8];
    const float* W_ih   = (const float*)d_in[9];
    const float* b_ih   = (const float*)d_in[10];
    const float* W_hh   = (const float*)d_in[11];
    const float* b_hh   = (const float*)d_in[12];
    const float* W_out  = (const float*)d_in[13];
    const float* b_out  = (const float*)d_in[14];
    float* out = (float*)d_out;

    init_h_kernel<<<(BB*DD + 255)/256, 256>>>(e_last);
    uk_gemm<<<dim3(8, 512), 256>>>(e_all, Ua, bu);

    for (int t = 0; t < TT; t++) {
        skinny_gemm<<<dim3(8, 4),  256>>>(Wa,   512, 512, 0);                 // q partials
        attn_kernel<<<BB, 512>>>(e_all, target, ba, Va_w, Va_b, out, t);      // w, ctx, gin
        skinny_gemm<<<dim3(24, 4), 256>>>(W_ih, KIN, GG, 1);                  // gi partials
        skinny_gemm<<<dim3(24, 4), 256>>>(W_hh, 512, GG, 2);                  // gh partials
        point_kernel<<<BB, 512>>>(b_ih, b_hh, W_out, b_out, out, t);          // h update + outputs
    }
}

// round 9
// speedup vs baseline: 1.5791x; 1.5791x over previous
#include <cuda_runtime.h>
#include <math.h>

#define BB   128
#define SS   512
#define DD   512
#define TT   64
#define OUTD 3
#define GG   (3*DD)        // 1536
#define KIN  (DD+OUTD)     // 515

typedef unsigned long long u64;

// ---------------- scratch (device globals: allocation-free) ----------------
__device__ float g_Uk[(size_t)BB*SS*DD];   // [B,S,D] tanh(Ua(keys)+bu)
__device__ float g_h  [BB*DD];             // decoder hidden state
__device__ float g_qp [4*BB*DD];           // split-K partials of q = h@Wa^T
__device__ float g_gin[BB*KIN];            // [ctx | x_t]
__device__ float g_gip[4*BB*GG];           // split-K partials of gi
__device__ float g_ghp[4*BB*GG];           // split-K partials of gh

// accurate-enough (≈1e-6) transcendentals (used OUTSIDE the hot loop)
__device__ __forceinline__ float tanh_fast(float x) {
    return 1.f - __fdividef(2.f, __expf(2.f*x) + 1.f);
}
__device__ __forceinline__ float sigmoid_fast(float x) {
    return __fdividef(1.f, 1.f + __expf(-x));
}

// ---- packed fp32x2 FMA helpers (sm_100+: fma.rn.f32x2) ----
__device__ __forceinline__ u64 bcast2(float x) {
    u64 d; asm("mov.b64 %0, {%1, %1};" : "=l"(d) : "f"(x)); return d;
}
__device__ __forceinline__ void ffma2(u64& acc, u64 a, u64 b) {
    asm("fma.rn.f32x2 %0, %1, %2, %0;" : "+l"(acc) : "l"(a), "l"(b));
}
__device__ __forceinline__ float2 unpack2(u64 v) {
    float2 f; asm("mov.b64 {%0, %1}, %2;" : "=f"(f.x), "=f"(f.y) : "l"(v)); return f;
}

// MUFU-free reciprocal for y in (0, 2]: bit-hack seed + 2 Newton steps (rel err ~6e-6)
__device__ __forceinline__ float rcp_fma(float y) {
    float r = __uint_as_float(0x7EF311C3u - __float_as_uint(y));
    r = r * fmaf(-y, r, 2.0f);
    r = r * fmaf(-y, r, 2.0f);
    return r;
}

// ---------------- init: h0 = e_last ----------------
__global__ void init_h_kernel(const float* __restrict__ e_last) {
    int i = blockIdx.x * blockDim.x + threadIdx.x;
    if (i < BB*DD) g_h[i] = e_last[i];
}

// ---------------- Uk GEMM: g_Uk[r,e] = tanh(sum_d e_all[r,d]*Ua[e,d] + bu[e])
// M=65536, N=512, K=512. BM=128, BN=64, BK=16, 256 threads, 8x4 per thread,
// accumulators held as 4 row-pairs x 4 cols in packed f32x2.
__global__ __launch_bounds__(256) void uk_gemm(const float* __restrict__ A,
                                               const float* __restrict__ W,
                                               const float* __restrict__ bias) {
    __shared__ __align__(16) float Xs[16][128];
    __shared__ __align__(16) float Ws[16][64];
    const int tid = threadIdx.x;
    const int tx = tid & 15, ty = tid >> 4;
    const int row0 = blockIdx.y * 128;
    const int n0   = blockIdx.x * 64;

    u64 acc2[4][4];
#pragma unroll
    for (int i = 0; i < 4; i++)
#pragma unroll
        for (int j = 0; j < 4; j++) acc2[i][j] = 0ull;

    for (int kc = 0; kc < 512; kc += 16) {
#pragma unroll
        for (int i = 0; i < 2; i++) {
            int l4 = tid*2 + i;                 // 0..511 float4 slots
            int r = l4 >> 2, kq = (l4 & 3) << 2;
            float4 v = *(const float4*)(A + (size_t)(row0 + r)*512 + kc + kq);
            Xs[kq+0][r] = v.x; Xs[kq+1][r] = v.y; Xs[kq+2][r] = v.z; Xs[kq+3][r] = v.w;
        }
        {
            int n = tid >> 2, kq = (tid & 3) << 2;
            float4 v = *(const float4*)(W + (size_t)(n0 + n)*512 + kc + kq);
            Ws[kq+0][n] = v.x; Ws[kq+1][n] = v.y; Ws[kq+2][n] = v.z; Ws[kq+3][n] = v.w;
        }
        __syncthreads();
#pragma unroll
        for (int kk = 0; kk < 16; kk++) {
            const u64* ap = (const u64*)&Xs[kk][ty*8];
            u64 a2[4], b2[4];
#pragma unroll
            for (int i = 0; i < 4; i++) a2[i] = ap[i];
#pragma unroll
            for (int j = 0; j < 4; j++) b2[j] = bcast2(Ws[kk][tx*4 + j]);
#pragma unroll
            for (int i = 0; i < 4; i++)
#pragma unroll
                for (int j = 0; j < 4; j++) ffma2(acc2[i][j], a2[i], b2[j]);
        }
        __syncthreads();
    }
#pragma unroll
    for (int i = 0; i < 4; i++) {
        size_t r0r = (size_t)(row0 + ty*8 + 2*i);
#pragma unroll
        for (int j = 0; j < 4; j++) {
            int n = n0 + tx*4 + j;
            float2 v = unpack2(acc2[i][j]);
            g_Uk[r0r*512 + n]     = tanh_fast(v.x + bias[n]);
            g_Uk[(r0r+1)*512 + n] = tanh_fast(v.y + bias[n]);
        }
    }
}

// ---------------- fused q + gh skinny GEMM (X = g_h, K=512), split-K=4 ----
// blockIdx.x < 8  -> q partials  (W=Wa,   N=512,  out g_qp)
// blockIdx.x >= 8 -> gh partials (W=W_hh, N=1536, out g_ghp)
__global__ __launch_bounds__(256) void qgh_gemm(const float* __restrict__ Wq,
                                                const float* __restrict__ Whh) {
    __shared__ __align__(16) float Xs[16][128];
    __shared__ __align__(16) float Ws[16][64];
    const int tid = threadIdx.x;
    const int tx = tid & 15, ty = tid >> 4;
    const int bx = blockIdx.x;
    const int part = blockIdx.y;
    const float* W; float* Cp; int n0, N;
    if (bx < 8) { W = Wq;  Cp = g_qp;  n0 = bx*64;      N = 512;  }
    else        { W = Whh; Cp = g_ghp; n0 = (bx-8)*64;  N = 1536; }
    const int kb = part * 128;

    u64 acc2[4][4];
#pragma unroll
    for (int i = 0; i < 4; i++)
#pragma unroll
        for (int j = 0; j < 4; j++) acc2[i][j] = 0ull;

    for (int kc = kb; kc < kb + 128; kc += 16) {
#pragma unroll
        for (int i = 0; i < 2; i++) {
            int l4 = tid*2 + i;
            int r = l4 >> 2, kq = (l4 & 3) << 2;
            float4 v = *(const float4*)(g_h + (size_t)r*512 + kc + kq);
            Xs[kq+0][r] = v.x; Xs[kq+1][r] = v.y; Xs[kq+2][r] = v.z; Xs[kq+3][r] = v.w;
        }
        {
            int n = tid >> 2, kq = (tid & 3) << 2;
            float4 v = *(const float4*)(W + (size_t)(n0 + n)*512 + kc + kq);
            Ws[kq+0][n] = v.x; Ws[kq+1][n] = v.y; Ws[kq+2][n] = v.z; Ws[kq+3][n] = v.w;
        }
        __syncthreads();
#pragma unroll
        for (int kk = 0; kk < 16; kk++) {
            const u64* ap = (const u64*)&Xs[kk][ty*8];
            u64 a2[4], b2[4];
#pragma unroll
            for (int i = 0; i < 4; i++) a2[i] = ap[i];
#pragma unroll
            for (int j = 0; j < 4; j++) b2[j] = bcast2(Ws[kk][tx*4 + j]);
#pragma unroll
            for (int i = 0; i < 4; i++)
#pragma unroll
                for (int j = 0; j < 4; j++) ffma2(acc2[i][j], a2[i], b2[j]);
        }
        __syncthreads();
    }
#pragma unroll
    for (int i = 0; i < 4; i++) {
        int b0 = ty*8 + 2*i;
        size_t base0 = ((size_t)part*BB + b0)     * (size_t)N + n0;
        size_t base1 = ((size_t)part*BB + b0 + 1) * (size_t)N + n0;
#pragma unroll
        for (int j = 0; j < 4; j++) {
            float2 v = unpack2(acc2[i][j]);
            Cp[base0 + tx*4 + j] = v.x;
            Cp[base1 + tx*4 + j] = v.y;
        }
    }
}

// ---------------- gi skinny GEMM (X = g_gin, K=515, N=1536), split-K=4 ----
__global__ __launch_bounds__(256) void gi_gemm(const float* __restrict__ W) {
    __shared__ __align__(16) float Xs[16][128];
    __shared__ __align__(16) float Ws[16][64];
    const int tid = threadIdx.x;
    const int tx = tid & 15, ty = tid >> 4;
    const int n0 = blockIdx.x * 64;
    const int part = blockIdx.y;
    const int K = KIN;
    const int chunk = (K + 3) >> 2;
    const int kb = part * chunk;
    const int ke = (kb + chunk < K) ? (kb + chunk) : K;

    u64 acc2[4][4];
#pragma unroll
    for (int i = 0; i < 4; i++)
#pragma unroll
        for (int j = 0; j < 4; j++) acc2[i][j] = 0ull;

    for (int kc = kb; kc < ke; kc += 16) {
#pragma unroll
        for (int i = 0; i < 8; i++) {
            int l = tid*8 + i;                  // 0..2047
            int r = l >> 4, k = l & 15;
            int kg = kc + k;
            Xs[k][r] = (kg < ke) ? g_gin[r*K + kg] : 0.f;
        }
#pragma unroll
        for (int i = 0; i < 4; i++) {
            int l = tid*4 + i;                  // 0..1023
            int n = l >> 4, k = l & 15;
            int kg = kc + k;
            Ws[k][n] = (kg < ke) ? W[(size_t)(n0 + n)*K + kg] : 0.f;
        }
        __syncthreads();
#pragma unroll
        for (int kk = 0; kk < 16; kk++) {
            const u64* ap = (const u64*)&Xs[kk][ty*8];
            u64 a2[4], b2[4];
#pragma unroll
            for (int i = 0; i < 4; i++) a2[i] = ap[i];
#pragma unroll
            for (int j = 0; j < 4; j++) b2[j] = bcast2(Ws[kk][tx*4 + j]);
#pragma unroll
            for (int i = 0; i < 4; i++)
#pragma unroll
                for (int j = 0; j < 4; j++) ffma2(acc2[i][j], a2[i], b2[j]);
        }
        __syncthreads();
    }
#pragma unroll
    for (int i = 0; i < 4; i++) {
        int b0 = ty*8 + 2*i;
        size_t base0 = ((size_t)part*BB + b0)     * (size_t)GG + n0;
        size_t base1 = ((size_t)part*BB + b0 + 1) * (size_t)GG + n0;
#pragma unroll
        for (int j = 0; j < 4; j++) {
            float2 v = unpack2(acc2[i][j]);
            g_gip[base0 + tx*4 + j] = v.x;
            g_gip[base1 + tx*4 + j] = v.y;
        }
    }
}

// per-element attention score term: va * tanh(q+u) via tanh addition formula.
// tu = tanh(u) (precomputed), tq = tanh(q). NO MUFU in this path.
__device__ __forceinline__ float attn_term(float tu, float tq, float va) {
    float y = fmaf(tq, tu, 1.0f);     // in (0, 2]
    float N = tq + tu;
    float r = rcp_fma(y);
    return va * (N * r);
}

// ---------------- attention: scores -> softmax -> ctx (one block per b) ---
__global__ __launch_bounds__(512) void attn_kernel(const float* __restrict__ e_all,
                                                   const float* __restrict__ target,
                                                   const float* __restrict__ ba,
                                                   const float* __restrict__ va,
                                                   const float* __restrict__ va_b,
                                                   float* __restrict__ out, int t) {
    const int b = blockIdx.x;
    const int tid = threadIdx.x;
    __shared__ __align__(16) float q_s[DD];    // holds tanh(q)
    __shared__ __align__(16) float w_s[SS];
    __shared__ float red[16];
    __shared__ float bval;

    // assemble q[b,:] = sum of split-K partials + ba, apply tanh
    {
        int off = b*DD + tid;
        float qv = ba[tid] + g_qp[off] + g_qp[BB*DD + off]
                 + g_qp[2*BB*DD + off] + g_qp[3*BB*DD + off];
        q_s[tid] = tanh_fast(qv);
    }
    __syncthreads();

    const int warp = tid >> 5, lane = tid & 31;
    // preload this lane's va / tanh(q) slices into registers
    float vreg[16], tqreg[16];
#pragma unroll
    for (int k = 0; k < 4; k++) {
        int d = lane*4 + k*128;
        float4 vv = *(const float4*)(va + d);
        float4 qq = *(const float4*)(&q_s[d]);
        vreg[k*4+0]=vv.x; vreg[k*4+1]=vv.y; vreg[k*4+2]=vv.z; vreg[k*4+3]=vv.w;
        tqreg[k*4+0]=qq.x; tqreg[k*4+1]=qq.y; tqreg[k*4+2]=qq.z; tqreg[k*4+3]=qq.w;
    }
    const float vb = va_b[0];

    // pass 1: scores (warp per s, 16 warps stride S). g_Uk already tanh'ed.
    for (int s = warp; s < SS; s += 16) {
        const float* u = g_Uk + ((size_t)b*SS + s)*DD;
        float acc = 0.f;
#pragma unroll
        for (int k = 0; k < 4; k++) {
            float4 uu = *(const float4*)(u + lane*4 + k*128);
            acc += attn_term(uu.x, tqreg[k*4+0], vreg[k*4+0]);
            acc += attn_term(uu.y, tqreg[k*4+1], vreg[k*4+1]);
            acc += attn_term(uu.z, tqreg[k*4+2], vreg[k*4+2]);
            acc += attn_term(uu.w, tqreg[k*4+3], vreg[k*4+3]);
        }
#pragma unroll
        for (int o = 16; o > 0; o >>= 1) acc += __shfl_xor_sync(0xffffffffu, acc, o);
        if (lane == 0) w_s[s] = acc + vb;
    }
    __syncthreads();

    // softmax over S (one thread per s)
    float sc = w_s[tid];
    float m = sc;
#pragma unroll
    for (int o = 16; o > 0; o >>= 1) m = fmaxf(m, __shfl_xor_sync(0xffffffffu, m, o));
    if (lane == 0) red[warp] = m;
    __syncthreads();
    if (tid == 0) {
        float mm = red[0];
#pragma unroll
        for (int i = 1; i < 16; i++) mm = fmaxf(mm, red[i]);
        bval = mm;
    }
    __syncthreads();
    float ex = __expf(sc - bval);
    float sm = ex;
#pragma unroll
    for (int o = 16; o > 0; o >>= 1) sm += __shfl_xor_sync(0xffffffffu, sm, o);
    if (lane == 0) red[warp] = sm;
    __syncthreads();
    if (tid == 0) {
        float tt = 0.f;
#pragma unroll
        for (int i = 0; i < 16; i++) tt += red[i];
        bval = tt;
    }
    __syncthreads();
    float wv = __fdividef(ex, bval);
    w_s[tid] = wv;
    out[(size_t)(BB*TT*OUTD + BB*DD) + ((size_t)b*TT + t)*SS + tid] = wv;
    __syncthreads();

    // pass 2: ctx[b,d] = sum_s w[s]*e_all[b,s,d]  (thread = d), unroll 8 for MLP
    const float* eb = e_all + (size_t)b*SS*DD + tid;
    float a0=0.f, a1=0.f, a2=0.f, a3=0.f, a4=0.f, a5=0.f, a6=0.f, a7=0.f;
    for (int s = 0; s < SS; s += 8) {
        a0 += w_s[s+0]*eb[(size_t)(s+0)*DD];
        a1 += w_s[s+1]*eb[(size_t)(s+1)*DD];
        a2 += w_s[s+2]*eb[(size_t)(s+2)*DD];
        a3 += w_s[s+3]*eb[(size_t)(s+3)*DD];
        a4 += w_s[s+4]*eb[(size_t)(s+4)*DD];
        a5 += w_s[s+5]*eb[(size_t)(s+5)*DD];
        a6 += w_s[s+6]*eb[(size_t)(s+6)*DD];
        a7 += w_s[s+7]*eb[(size_t)(s+7)*DD];
    }
    g_gin[b*KIN + tid] = ((a0+a1)+(a2+a3)) + ((a4+a5)+(a6+a7));
    // teacher-forced decoder input (attn first, x second)
    if (tid < OUTD)
        g_gin[b*KIN + DD + tid] = (t == 0) ? 0.f
                                  : target[((size_t)b*TT + (t-1))*OUTD + tid];
}

// ---------------- GRU pointwise + output projection (block per b) ---------
__global__ __launch_bounds__(512) void point_kernel(const float* __restrict__ b_ih,
                                                    const float* __restrict__ b_hh,
                                                    const float* __restrict__ W_out,
                                                    const float* __restrict__ b_out,
                                                    float* __restrict__ out, int t) {
    const int b = blockIdx.x, d = threadIdx.x;
    const int base = b*DD + d;

    float ir = b_ih[d], iz = b_ih[DD+d], in_ = b_ih[2*DD+d];
    float hr = b_hh[d], hz = b_hh[DD+d], hn  = b_hh[2*DD+d];
#pragma unroll
    for (int p = 0; p < 4; p++) {
        size_t o = ((size_t)p*BB + b)*GG;
        ir += g_gip[o + d]; iz += g_gip[o + DD + d]; in_ += g_gip[o + 2*DD + d];
        hr += g_ghp[o + d]; hz += g_ghp[o + DD + d]; hn  += g_ghp[o + 2*DD + d];
    }
    float r = sigmoid_fast(ir + hr);
    float z = sigmoid_fast(iz + hz);
    float n = tanh_fast(in_ + r*hn);
    float hp = g_h[base];
    float hnew = (1.f - z)*n + z*hp;
    g_h[base] = hnew;
    if (t == TT-1) out[BB*TT*OUTD + base] = hnew;   // hT region

    // out = h_new @ W_out^T + b_out  (3 block-wide dot products)
    float p0 = hnew*W_out[d], p1 = hnew*W_out[DD+d], p2 = hnew*W_out[2*DD+d];
#pragma unroll
    for (int o = 16; o > 0; o >>= 1) {
        p0 += __shfl_xor_sync(0xffffffffu, p0, o);
        p1 += __shfl_xor_sync(0xffffffffu, p1, o);
        p2 += __shfl_xor_sync(0xffffffffu, p2, o);
    }
    __shared__ float r0[16], r1[16], r2[16];
    int warp = d >> 5, lane = d & 31;
    if (lane == 0) { r0[warp] = p0; r1[warp] = p1; r2[warp] = p2; }
    __syncthreads();
    if (d == 0) {
        float s0=0.f, s1=0.f, s2=0.f;
#pragma unroll
        for (int i = 0; i < 16; i++) { s0 += r0[i]; s1 += r1[i]; s2 += r2[i]; }
        size_t ob = ((size_t)b*TT + t)*OUTD;
        out[ob+0] = s0 + b_out[0];
        out[ob+1] = s1 + b_out[1];
        out[ob+2] = s2 + b_out[2];
    }
}

// ---------------- host launcher -------------------------------------------
extern "C" void kernel_launch(void* const* d_in, const int* in_sizes, int n_in,
                              void* d_out, int out_size) {
    (void)in_sizes; (void)n_in; (void)out_size;
    const float* e_all  = (const float*)d_in[0];
    const float* e_last = (const float*)d_in[1];
    const float* target = (const float*)d_in[2];
    const float* Wa     = (const float*)d_in[3];
    const float* ba     = (const float*)d_in[4];
    const float* Ua     = (const float*)d_in[5];
    const float* bu     = (const float*)d_in[6];
    const float* Va_w   = (const float*)d_in[7];
    const float* Va_b   = (const float*)d_in[8];
    const float* W_ih   = (const float*)d_in[9];
    const float* b_ih   = (const float*)d_in[10];
    const float* W_hh   = (const float*)d_in[11];
    const float* b_hh   = (const float*)d_in[12];
    const float* W_out  = (const float*)d_in[13];
    const float* b_out  = (const float*)d_in[14];
    float* out = (float*)d_out;

    init_h_kernel<<<(BB*DD + 255)/256, 256>>>(e_last);
    uk_gemm<<<dim3(8, 512), 256>>>(e_all, Ua, bu);

    for (int t = 0; t < TT; t++) {
        qgh_gemm<<<dim3(32, 4), 256>>>(Wa, W_hh);                             // q + gh partials
        attn_kernel<<<BB, 512>>>(e_all, target, ba, Va_w, Va_b, out, t);      // w, ctx, gin
        gi_gemm<<<dim3(24, 4), 256>>>(W_ih);                                  // gi partials
        point_kernel<<<BB, 512>>>(b_ih, b_hh, W_out, b_out, out, t);          // h update + outputs
    }
}